// round 5
// baseline (speedup 1.0000x reference)
#include <cuda_runtime.h>
#include <cuda_fp16.h>

// ---------------- problem constants ----------------
#define HH   256
#define H2   512
#define GG   64
#define NNODE 20000
#define NEDGE 320000

// ---------------- tile config ----------------------
#define TM      64
#define THREADS 256

#define ALD 260                          // fp32 words per A row (conflict-free frags)
#define HLD 516                          // fp16 elems per hidden row
#define WLD 136                          // fp32 words per weight-tile row (conflict-free B frags)
#define AS_BYTES (TM * ALD * 4)          // 66560
#define HS_BYTES (TM * HLD * 2)          // 66048
#define WBUF_BYTES (32 * WLD * 4)        // 17408
#define AS_OFF 0
#define HS_OFF (AS_OFF + AS_BYTES)
#define WS_OFF (HS_OFF + HS_BYTES)
#define B1_OFF (WS_OFF + 2 * WBUF_BYTES)
#define B2_OFF (B1_OFF + H2 * 4)
#define SMEM_BYTES (B2_OFF + HH * 4)     // 170496 < 227KB

// ---------------- device scratch (no cudaMalloc allowed) ----------------
// tf32-rounded weights: [node_w1, node_w2, glob_w1, glob_w2, edge_w1, edge_w2]
__device__ __align__(16) float g_wr[6 * 131072];
__device__ __align__(16) float g_gf[GG * HH];   // segment-mean global features

// ---------------- helpers ----------------
__device__ __forceinline__ unsigned t32(float x) {
    unsigned u;
    asm("cvt.rna.tf32.f32 %0, %1;" : "=r"(u) : "f"(x));
    return u;
}

__device__ __forceinline__ float gelu_tanh(float x) {
    // matches jax.nn.gelu(approximate=True)
    float t = tanhf(0.7978845608028654f * (x + 0.044715f * x * x * x));
    return 0.5f * x * (1.0f + t);
}

__device__ __forceinline__ void mma8(float* c, const unsigned* a, unsigned b0, unsigned b1) {
    asm volatile(
        "mma.sync.aligned.m16n8k8.row.col.f32.tf32.tf32.f32 "
        "{%0,%1,%2,%3}, {%4,%5,%6,%7}, {%8,%9}, {%0,%1,%2,%3};\n"
        : "+f"(c[0]), "+f"(c[1]), "+f"(c[2]), "+f"(c[3])
        : "r"(a[0]), "r"(a[1]), "r"(a[2]), "r"(a[3]), "r"(b0), "r"(b1));
}

#define CP_COMMIT asm volatile("cp.async.commit_group;\n")
#define CP_WAIT1  asm volatile("cp.async.wait_group 1;\n")
#define CP_WAIT0  asm volatile("cp.async.wait_group 0;\n")

// copy one [32 x 128] fp32 weight tile into smem buffer `buf`
__device__ __forceinline__ void copy_tile(char* smem, int buf, const float* __restrict__ gsrc,
                                          int ldw, int k0, int n0) {
    unsigned sb = (unsigned)__cvta_generic_to_shared(smem + WS_OFF + buf * WBUF_BYTES);
    int tid = threadIdx.x;
#pragma unroll
    for (int it = 0; it < 4; ++it) {
        int idx = tid + it * THREADS;          // 0..1023 vec4s
        int row = idx >> 5;                    // 0..31
        int cv  = idx & 31;                    // 0..31
        unsigned sa = sb + row * (WLD * 4) + cv * 16;
        const float* gp = gsrc + (size_t)(k0 + row) * ldw + n0 + cv * 4;
        asm volatile("cp.async.cg.shared.global [%0], [%1], 16;\n" ::"r"(sa), "l"(gp));
    }
}

// ---------------- prep: tf32-round all 6 weight matrices ----------------
__global__ void prep_kernel(const float* __restrict__ p0, const float* __restrict__ p1,
                            const float* __restrict__ p2, const float* __restrict__ p3,
                            const float* __restrict__ p4, const float* __restrict__ p5) {
    int i = blockIdx.x * blockDim.x + threadIdx.x;   // 786432 total
    int w = i >> 17;
    const float* src = (w == 0) ? p0 : (w == 1) ? p1 : (w == 2) ? p2
                      : (w == 3) ? p3 : (w == 4) ? p4 : p5;
    g_wr[i] = __uint_as_float(t32(src[i & 131071]));
}

// ---------------- segment mean (node_batch is sorted) ----------------
__global__ void seg_mean_kernel(const float* __restrict__ nf, const int* __restrict__ batch,
                                int n) {
    int gid = blockIdx.x;
    int lo, hi;
    { int a = 0, b = n; while (a < b) { int m = (a + b) >> 1; if (batch[m] <  gid) a = m + 1; else b = m; } lo = a; }
    { int a = lo, b = n; while (a < b) { int m = (a + b) >> 1; if (batch[m] <= gid) a = m + 1; else b = m; } hi = a; }
    int col = threadIdx.x;
    float s = 0.f;
    for (int r = lo; r < hi; ++r) s += nf[(size_t)r * HH + col];
    g_gf[gid * HH + col] = s / fmaxf((float)(hi - lo), 1.0f);
}

// ---------------- fused LN -> FFN -> residual ----------------
// out[r] = X[r] + W2^T gelu(W1^T LN(X[r]) + b1) + b2
__global__ void __launch_bounds__(THREADS, 1)
ffn_kernel(const float* __restrict__ Xp, long R,
           const float* __restrict__ gamma, const float* __restrict__ beta,
           int woff,
           const float* __restrict__ bias1, const float* __restrict__ bias2,
           float* __restrict__ out, int use_gf) {
    extern __shared__ char smem[];
    const float* X  = use_gf ? g_gf : Xp;
    const float* w1 = g_wr + woff;
    const float* w2 = g_wr + woff + 131072;

    unsigned* AsU = (unsigned*)(smem + AS_OFF);
    __half*   Hs  = (__half*)(smem + HS_OFF);
    float*    b1s = (float*)(smem + B1_OFF);
    float*    b2s = (float*)(smem + B2_OFF);

    int tid = threadIdx.x;
    int warp = tid >> 5, lane = tid & 31;
    int g = lane >> 2, tig = lane & 3;
    int wm = warp >> 2, wn = warp & 3;     // 2 m-warps x 4 n-warps
    int m0 = wm * 32;
    long base = (long)blockIdx.x * TM;

    for (int i = tid; i < H2; i += THREADS) b1s[i] = bias1[i];
    for (int i = tid; i < HH; i += THREADS) b2s[i] = bias2[i];

    // ---- LayerNorm: one warp per row-group of 8 rows, coalesced float4 ----
    float4 gm0 = *(const float4*)(gamma + lane * 4);
    float4 gm1 = *(const float4*)(gamma + 128 + lane * 4);
    float4 bt0 = *(const float4*)(beta + lane * 4);
    float4 bt1 = *(const float4*)(beta + 128 + lane * 4);
#pragma unroll
    for (int rr = 0; rr < 8; ++rr) {
        int row = warp * 8 + rr;
        long gr = base + row;
        float4 v0 = make_float4(0.f, 0.f, 0.f, 0.f);
        float4 v1 = make_float4(0.f, 0.f, 0.f, 0.f);
        if (gr < R) {
            v0 = *(const float4*)(X + gr * HH + lane * 4);
            v1 = *(const float4*)(X + gr * HH + 128 + lane * 4);
        }
        float s = v0.x + v0.y + v0.z + v0.w + v1.x + v1.y + v1.z + v1.w;
        float q = v0.x * v0.x + v0.y * v0.y + v0.z * v0.z + v0.w * v0.w
                + v1.x * v1.x + v1.y * v1.y + v1.z * v1.z + v1.w * v1.w;
#pragma unroll
        for (int o = 16; o; o >>= 1) {
            s += __shfl_xor_sync(0xFFFFFFFFu, s, o);
            q += __shfl_xor_sync(0xFFFFFFFFu, q, o);
        }
        float mean = s * (1.0f / HH);
        float var  = q * (1.0f / HH) - mean * mean;
        float rstd = rsqrtf(var + 1e-5f);
        unsigned* Ar = AsU + row * ALD;
        Ar[lane * 4 + 0] = t32((v0.x - mean) * rstd * gm0.x + bt0.x);
        Ar[lane * 4 + 1] = t32((v0.y - mean) * rstd * gm0.y + bt0.y);
        Ar[lane * 4 + 2] = t32((v0.z - mean) * rstd * gm0.z + bt0.z);
        Ar[lane * 4 + 3] = t32((v0.w - mean) * rstd * gm0.w + bt0.w);
        Ar[128 + lane * 4 + 0] = t32((v1.x - mean) * rstd * gm1.x + bt1.x);
        Ar[128 + lane * 4 + 1] = t32((v1.y - mean) * rstd * gm1.y + bt1.y);
        Ar[128 + lane * 4 + 2] = t32((v1.z - mean) * rstd * gm1.z + bt1.z);
        Ar[128 + lane * 4 + 3] = t32((v1.w - mean) * rstd * gm1.w + bt1.w);
    }
    __syncthreads();

    float acc[2][4][4];

    // ================= GEMM1: H1[64,512] = As[64,256] @ w1[256,512], GELU -> Hs =================
#pragma unroll 1
    for (int nc = 0; nc < 4; ++nc) {
#pragma unroll
        for (int mt = 0; mt < 2; ++mt)
#pragma unroll
            for (int nt = 0; nt < 4; ++nt)
#pragma unroll
                for (int i = 0; i < 4; ++i) acc[mt][nt][i] = 0.f;
        int n0g = nc * 128;
        copy_tile(smem, 0, w1, H2, 0, n0g);
        CP_COMMIT;
#pragma unroll 1
        for (int kt = 0; kt < 8; ++kt) {
            int cur = kt & 1;
            if (kt + 1 < 8) {
                copy_tile(smem, cur ^ 1, w1, H2, (kt + 1) * 32, n0g);
                CP_COMMIT;
                CP_WAIT1;
            } else {
                CP_WAIT0;
            }
            __syncthreads();
            const unsigned* Ws = (const unsigned*)(smem + WS_OFF + cur * WBUF_BYTES);
#pragma unroll
            for (int ks = 0; ks < 4; ++ks) {
                int k = kt * 32 + ks * 8;
                unsigned a[2][4];
#pragma unroll
                for (int mt = 0; mt < 2; ++mt) {
                    int r = m0 + mt * 16 + g;
                    a[mt][0] = AsU[r * ALD + k + tig];
                    a[mt][1] = AsU[(r + 8) * ALD + k + tig];
                    a[mt][2] = AsU[r * ALD + k + tig + 4];
                    a[mt][3] = AsU[(r + 8) * ALD + k + tig + 4];
                }
#pragma unroll
                for (int nt = 0; nt < 4; ++nt) {
                    int c = wn * 32 + nt * 8 + g;
                    unsigned b0 = Ws[(ks * 8 + tig) * WLD + c];
                    unsigned b1 = Ws[(ks * 8 + tig + 4) * WLD + c];
                    mma8(acc[0][nt], a[0], b0, b1);
                    mma8(acc[1][nt], a[1], b0, b1);
                }
            }
            __syncthreads();
        }
        // epilogue: bias + GELU -> Hs (fp16)
#pragma unroll
        for (int mt = 0; mt < 2; ++mt) {
            int r = m0 + mt * 16 + g;
#pragma unroll
            for (int nt = 0; nt < 4; ++nt) {
                int col = n0g + wn * 32 + nt * 8 + 2 * tig;
                float h0 = gelu_tanh(acc[mt][nt][0] + b1s[col]);
                float h1 = gelu_tanh(acc[mt][nt][1] + b1s[col + 1]);
                float h2 = gelu_tanh(acc[mt][nt][2] + b1s[col]);
                float h3 = gelu_tanh(acc[mt][nt][3] + b1s[col + 1]);
                *(__half2*)(Hs + (size_t)r * HLD + col)       = __floats2half2_rn(h0, h1);
                *(__half2*)(Hs + (size_t)(r + 8) * HLD + col) = __floats2half2_rn(h2, h3);
            }
        }
    }
    __syncthreads();

    // ================= GEMM2: O[64,256] = Hs[64,512] @ w2[512,256] + b2 + X =================
#pragma unroll 1
    for (int nc = 0; nc < 2; ++nc) {
#pragma unroll
        for (int mt = 0; mt < 2; ++mt)
#pragma unroll
            for (int nt = 0; nt < 4; ++nt)
#pragma unroll
                for (int i = 0; i < 4; ++i) acc[mt][nt][i] = 0.f;
        int n0g = nc * 128;
        copy_tile(smem, 0, w2, HH, 0, n0g);
        CP_COMMIT;
#pragma unroll 1
        for (int kt = 0; kt < 16; ++kt) {
            int cur = kt & 1;
            if (kt + 1 < 16) {
                copy_tile(smem, cur ^ 1, w2, HH, (kt + 1) * 32, n0g);
                CP_COMMIT;
                CP_WAIT1;
            } else {
                CP_WAIT0;
            }
            __syncthreads();
            const unsigned* Ws = (const unsigned*)(smem + WS_OFF + cur * WBUF_BYTES);
#pragma unroll
            for (int ks = 0; ks < 4; ++ks) {
                int k = kt * 32 + ks * 8;
                unsigned a[2][4];
#pragma unroll
                for (int mt = 0; mt < 2; ++mt) {
                    int r = m0 + mt * 16 + g;
                    a[mt][0] = t32(__half2float(Hs[(size_t)r * HLD + k + tig]));
                    a[mt][1] = t32(__half2float(Hs[(size_t)(r + 8) * HLD + k + tig]));
                    a[mt][2] = t32(__half2float(Hs[(size_t)r * HLD + k + tig + 4]));
                    a[mt][3] = t32(__half2float(Hs[(size_t)(r + 8) * HLD + k + tig + 4]));
                }
#pragma unroll
                for (int nt = 0; nt < 4; ++nt) {
                    int c = wn * 32 + nt * 8 + g;
                    unsigned b0 = Ws[(ks * 8 + tig) * WLD + c];
                    unsigned b1 = Ws[(ks * 8 + tig + 4) * WLD + c];
                    mma8(acc[0][nt], a[0], b0, b1);
                    mma8(acc[1][nt], a[1], b0, b1);
                }
            }
            __syncthreads();
        }
        // epilogue: bias + residual, store float2
#pragma unroll
        for (int mt = 0; mt < 2; ++mt) {
            int r = m0 + mt * 16 + g;
            long gr0 = base + r;
            long gr1 = gr0 + 8;
#pragma unroll
            for (int nt = 0; nt < 4; ++nt) {
                int col = n0g + wn * 32 + nt * 8 + 2 * tig;
                if (gr0 < R) {
                    float2 x = *(const float2*)(X + gr0 * HH + col);
                    float2 o = make_float2(acc[mt][nt][0] + b2s[col] + x.x,
                                           acc[mt][nt][1] + b2s[col + 1] + x.y);
                    *(float2*)(out + gr0 * HH + col) = o;
                }
                if (gr1 < R) {
                    float2 x = *(const float2*)(X + gr1 * HH + col);
                    float2 o = make_float2(acc[mt][nt][2] + b2s[col] + x.x,
                                           acc[mt][nt][3] + b2s[col + 1] + x.y);
                    *(float2*)(out + gr1 * HH + col) = o;
                }
            }
        }
    }
}

// ---------------- launch ----------------
extern "C" void kernel_launch(void* const* d_in, const int* in_sizes, int n_in,
                              void* d_out, int out_size) {
    const float* nodef = (const float*)d_in[0];
    const float* edgef = (const float*)d_in[1];
    const int*   batch = (const int*)d_in[2];
    // 18 param arrays at the tail: 3 groups x [norm_g, norm_b, w1, b1, w2, b2]
    int pb = n_in - 18;
    const float* P[18];
    for (int i = 0; i < 18; ++i) P[i] = (const float*)d_in[pb + i];

    float* out   = (float*)d_out;
    float* out_g = out;                               // [64, 256]
    float* out_n = out + (size_t)GG * HH;             // [20000, 256]
    float* out_e = out_n + (size_t)NNODE * HH;        // [320000, 256]

    cudaFuncSetAttribute(ffn_kernel, cudaFuncAttributeMaxDynamicSharedMemorySize, SMEM_BYTES);

    // tf32-round weights: node_w1, node_w2, glob_w1, glob_w2, edge_w1, edge_w2
    prep_kernel<<<3072, 256>>>(P[2], P[4], P[8], P[10], P[14], P[16]);

    // global features = segment mean of node features
    seg_mean_kernel<<<GG, HH>>>(nodef, batch, NNODE);

    // global readout (reads g_gf)
    ffn_kernel<<<1, THREADS, SMEM_BYTES>>>(
        nullptr, (long)GG, P[6], P[7], 2 * 131072, P[9], P[11], out_g, 1);

    // node readout
    ffn_kernel<<<(NNODE + TM - 1) / TM, THREADS, SMEM_BYTES>>>(
        nodef, (long)NNODE, P[0], P[1], 0, P[3], P[5], out_n, 0);

    // edge readout (viewed as [320000, 256])
    ffn_kernel<<<NEDGE / TM, THREADS, SMEM_BYTES>>>(
        edgef, (long)NEDGE, P[12], P[13], 4 * 131072, P[15], P[17], out_e, 0);
}